// round 14
// baseline (speedup 1.0000x reference)
#include <cuda_runtime.h>
#include <cuda_bf16.h>
#include <cuda_fp16.h>
#include <stdint.h>

#define MAX_N 50000
#define MAX_E 800000
#define SLOTS 96          // fixed bucket capacity; deg ~ Poisson(16), P(>96) ~ 0

// ---------------- scratch ----------------
__device__ int   g_cnt[MAX_N];
__device__ int   g_slot[(size_t)MAX_N * SLOTS];
__device__ float g_dinv[MAX_N];
__device__ __align__(16) __half g_x16[(size_t)MAX_N * 128];
__device__ __align__(16) __half g_a16[(size_t)MAX_N * 256];
__device__ __align__(16) __half g_h16[(size_t)MAX_N * 256];
// fp16 weights, transposed [n][k]; Wl pre-scaled by 512 (subnormal-safe)
__device__ __half g_W1h[256 * 128];
__device__ __half g_W1l[256 * 128];
__device__ __half g_W2h[256 * 256];
__device__ __half g_W2l[256 * 256];

// ---------------- fused setup: zero cnt + weight split + x->fp16 ----------
__global__ void setup_kernel(const float* __restrict__ x,
                             const float* __restrict__ W1, const float* __restrict__ W2,
                             __half* __restrict__ W1h, __half* __restrict__ W1l,
                             __half* __restrict__ W2h, __half* __restrict__ W2l,
                             __half* __restrict__ x16, int n) {
    int i = blockIdx.x * blockDim.x + threadIdx.x;
    if (i < n) g_cnt[i] = 0;
    if (i < 256 * 128) {
        int nn = i >> 7, k = i & 127;
        float w = W1[k * 256 + nn];
        __half h = __float2half_rn(w);
        W1h[i] = h;
        W1l[i] = __float2half_rn((w - __half2float(h)) * 512.0f);
    }
    if (i < 256 * 256) {
        int nn = i >> 8, k = i & 255;
        float w = W2[k * 256 + nn];
        __half h = __float2half_rn(w);
        W2h[i] = h;
        W2l[i] = __float2half_rn((w - __half2float(h)) * 512.0f);
    }
    if (i < n * 32) {
        float4 v = ((const float4*)x)[i];
        uint2 o;
        __half2 p0 = __floats2half2_rn(v.x, v.y);
        __half2 p1 = __floats2half2_rn(v.z, v.w);
        o.x = *(uint32_t*)&p0;
        o.y = *(uint32_t*)&p1;
        ((uint2*)x16)[i] = o;
    }
}

// ---------------- single-pass bucket CSR build (count + scatter) ----------
__global__ void fill8_kernel(const int* __restrict__ ei, int e) {
    int i = (blockIdx.x * blockDim.x + threadIdx.x) * 8;
    if (i + 7 < e) {
        int4 s0 = *(const int4*)(ei + i);
        int4 s1 = *(const int4*)(ei + i + 4);
        int4 d0 = *(const int4*)(ei + e + i);
        int4 d1 = *(const int4*)(ei + e + i + 4);
        int p0 = atomicAdd(&g_cnt[d0.x], 1);
        int p1 = atomicAdd(&g_cnt[d0.y], 1);
        int p2 = atomicAdd(&g_cnt[d0.z], 1);
        int p3 = atomicAdd(&g_cnt[d0.w], 1);
        int p4 = atomicAdd(&g_cnt[d1.x], 1);
        int p5 = atomicAdd(&g_cnt[d1.y], 1);
        int p6 = atomicAdd(&g_cnt[d1.z], 1);
        int p7 = atomicAdd(&g_cnt[d1.w], 1);
        if (p0 < SLOTS) g_slot[(size_t)d0.x * SLOTS + p0] = s0.x;
        if (p1 < SLOTS) g_slot[(size_t)d0.y * SLOTS + p1] = s0.y;
        if (p2 < SLOTS) g_slot[(size_t)d0.z * SLOTS + p2] = s0.z;
        if (p3 < SLOTS) g_slot[(size_t)d0.w * SLOTS + p3] = s0.w;
        if (p4 < SLOTS) g_slot[(size_t)d1.x * SLOTS + p4] = s1.x;
        if (p5 < SLOTS) g_slot[(size_t)d1.y * SLOTS + p5] = s1.y;
        if (p6 < SLOTS) g_slot[(size_t)d1.z * SLOTS + p6] = s1.z;
        if (p7 < SLOTS) g_slot[(size_t)d1.w * SLOTS + p7] = s1.w;
    } else {
        for (int j = i; j < e; j++) {
            int src = ei[j];
            int d = ei[e + j];
            int pos = atomicAdd(&g_cnt[d], 1);
            if (pos < SLOTS) g_slot[(size_t)d * SLOTS + pos] = src;
        }
    }
}
__global__ void fill1_kernel(const int* __restrict__ ei, int e) {
    int i = blockIdx.x * blockDim.x + threadIdx.x;
    if (i < e) {
        int src = ei[i];
        int d = ei[e + i];
        int pos = atomicAdd(&g_cnt[d], 1);
        if (pos < SLOTS) g_slot[(size_t)d * SLOTS + pos] = src;
    }
}

// dinv from final counts
__global__ void dinv_kernel(int n) {
    int i = blockIdx.x * blockDim.x + threadIdx.x;
    if (i < n) g_dinv[i] = rsqrtf((float)(g_cnt[i] + 1));
}

// ---------------- fp16 aggregation: shfl-preload + HFMA2 dual-bank accum ---
template <int F>
__global__ void agg_f16_kernel(const __half* __restrict__ xh, __half* __restrict__ out, int n) {
    int warp = blockIdx.x * (blockDim.x >> 5) + (threadIdx.x >> 5);
    int lane = threadIdx.x & 31;
    if (warp >= n) return;
    constexpr int V2 = F / 64;        // half2 words per lane: 2 or 4
    float di = g_dinv[warp];
    const uint32_t* __restrict__ xw = (const uint32_t*)xh;

    // self term in fp32: fself = di * x_self
    float fself[2 * V2];
    #pragma unroll
    for (int v = 0; v < V2; v++) {
        uint32_t u = xw[(size_t)warp * (F / 2) + lane * V2 + v];
        float2 t = __half22float2(*(__half2*)&u);
        fself[2 * v] = di * t.x;
        fself[2 * v + 1] = di * t.y;
    }

    // fp16 dual-bank accumulators for sum w_s x_s
    __half2 accA[V2], accB[V2];
    #pragma unroll
    for (int v = 0; v < V2; v++) {
        accA[v] = __floats2half2_rn(0.f, 0.f);
        accB[v] = __floats2half2_rn(0.f, 0.f);
    }

    int deg = g_cnt[warp];
    if (deg > SLOTS) deg = SLOTS;
    const int* __restrict__ sl = g_slot + (size_t)warp * SLOTS;

    // per-lane preload: slot + its dinv pre-packed as half2 (broadcast pair)
    int pslot = (lane < deg) ? sl[lane] : 0;
    float pwf = (lane < deg) ? g_dinv[pslot] : 0.f;
    __half2 pwh = __float2half2_rn(pwf);
    uint32_t pw = *(uint32_t*)&pwh;

    auto ldrow = [&](uint32_t* u, int s) {
        if constexpr (V2 == 4) {
            uint4 a = *(const uint4*)(xw + (size_t)s * (F / 2) + lane * 4);
            u[0] = a.x; u[1] = a.y; u[2] = a.z; u[3] = a.w;
        } else {
            uint2 a = *(const uint2*)(xw + (size_t)s * (F / 2) + lane * 2);
            u[0] = a.x; u[1] = a.y;
        }
    };

    int dfast = deg < 32 ? deg : 32;
    int e = 0;
    for (; e + 3 < dfast; e += 4) {
        int s0 = __shfl_sync(0xffffffffu, pslot, e);
        int s1 = __shfl_sync(0xffffffffu, pslot, e + 1);
        int s2 = __shfl_sync(0xffffffffu, pslot, e + 2);
        int s3 = __shfl_sync(0xffffffffu, pslot, e + 3);
        uint32_t w0 = __shfl_sync(0xffffffffu, pw, e);
        uint32_t w1 = __shfl_sync(0xffffffffu, pw, e + 1);
        uint32_t w2 = __shfl_sync(0xffffffffu, pw, e + 2);
        uint32_t w3 = __shfl_sync(0xffffffffu, pw, e + 3);
        uint32_t u0[V2], u1[V2], u2[V2], u3[V2];
        ldrow(u0, s0); ldrow(u1, s1); ldrow(u2, s2); ldrow(u3, s3);
        #pragma unroll
        for (int v = 0; v < V2; v++) {
            accA[v] = __hfma2(*(__half2*)&w0, *(__half2*)&u0[v], accA[v]);
            accB[v] = __hfma2(*(__half2*)&w1, *(__half2*)&u1[v], accB[v]);
        }
        #pragma unroll
        for (int v = 0; v < V2; v++) {
            accA[v] = __hfma2(*(__half2*)&w2, *(__half2*)&u2[v], accA[v]);
            accB[v] = __hfma2(*(__half2*)&w3, *(__half2*)&u3[v], accB[v]);
        }
    }
    for (; e < dfast; e++) {
        int s = __shfl_sync(0xffffffffu, pslot, e);
        uint32_t w = __shfl_sync(0xffffffffu, pw, e);
        uint32_t u[V2];
        ldrow(u, s);
        #pragma unroll
        for (int v = 0; v < V2; v++)
            accA[v] = __hfma2(*(__half2*)&w, *(__half2*)&u[v], accA[v]);
    }
    for (; e < deg; e++) {            // rare tail: deg > 32
        int s = sl[e];
        __half2 w = __float2half2_rn(g_dinv[s]);
        uint32_t u[V2];
        ldrow(u, s);
        #pragma unroll
        for (int v = 0; v < V2; v++)
            accB[v] = __hfma2(w, *(__half2*)&u[v], accB[v]);
    }

    // combine in fp32: out = di * (fself + accA + accB)
    __half2* op = (__half2*)(out + (size_t)warp * F + lane * 2 * V2);
    #pragma unroll
    for (int v = 0; v < V2; v++) {
        float2 a = __half22float2(accA[v]);
        float2 b = __half22float2(accB[v]);
        float ox = di * (fself[2 * v] + a.x + b.x);
        float oy = di * (fself[2 * v + 1] + a.y + b.y);
        op[v] = __floats2half2_rn(ox, oy);
    }
}

// ---------------- fp16 tensor GEMM: ldmatrix + cp.async, KC=64 ------------
__device__ __forceinline__ void mma_f16(float* c, const uint32_t* a, uint32_t b0, uint32_t b1) {
    asm volatile(
        "mma.sync.aligned.m16n8k16.row.col.f32.f16.f16.f32 "
        "{%0,%1,%2,%3}, {%4,%5,%6,%7}, {%8,%9}, {%0,%1,%2,%3};"
        : "+f"(c[0]), "+f"(c[1]), "+f"(c[2]), "+f"(c[3])
        : "r"(a[0]), "r"(a[1]), "r"(a[2]), "r"(a[3]), "r"(b0), "r"(b1));
}
__device__ __forceinline__ void ldsm4(uint32_t* r, uint32_t addr) {
    asm volatile("ldmatrix.sync.aligned.m8n8.x4.shared.b16 {%0,%1,%2,%3}, [%4];"
                 : "=r"(r[0]), "=r"(r[1]), "=r"(r[2]), "=r"(r[3]) : "r"(addr));
}
__device__ __forceinline__ void cp16(uint32_t dst, const void* src) {
    asm volatile("cp.async.cg.shared.global [%0], [%1], 16;" :: "r"(dst), "l"(src));
}
__device__ __forceinline__ uint32_t smem_u32(const void* p) {
    uint32_t a;
    asm("{.reg .u64 t; cvta.to.shared.u64 t, %1; cvt.u32.u64 %0, t;}" : "=r"(a) : "l"(p));
    return a;
}

#define KC 64
#define ROWB 144
#define ARRB (128 * ROWB)
#define BUFB (3 * ARRB)
#define GEMM_SMEM (2 * BUFB)

template <int K>
__global__ __launch_bounds__(256, 2)
void gemm_f16(const __half* __restrict__ A, const __half* __restrict__ Wh,
              const __half* __restrict__ Wl, const float* __restrict__ bias,
              __half* __restrict__ C16, int M) {
    extern __shared__ __half smem[];
    const uint32_t sbase = smem_u32(smem);
    const int tid = threadIdx.x;
    const int wid = tid >> 5;
    const int lane = tid & 31;
    const int row0 = blockIdx.x * 128;
    const int colbase = blockIdx.y * 128;
    const int m_off = (wid & 3) * 32;
    const int n_off = (wid >> 2) * 64;
    const __half2 inv512 = __half2half2(__float2half(0.001953125f));
    constexpr int CHUNKS = K / KC;

    float acc[2][8][4];
    #pragma unroll
    for (int mt = 0; mt < 2; mt++)
        #pragma unroll
        for (int nt = 0; nt < 8; nt++)
            #pragma unroll
            for (int q = 0; q < 4; q++) acc[mt][nt][q] = 0.f;

    auto stage = [&](int c, int b) {
        int k0 = c * KC;
        uint32_t buf = sbase + b * BUFB;
        #pragma unroll
        for (int it = 0; it < 4; it++) {
            int i = tid + it * 256;
            int r = i >> 3;
            int q = (i & 7) * 8;
            int rr = row0 + r; if (rr >= M) rr = M - 1;
            cp16(buf + r * ROWB + q * 2, A + (size_t)rr * K + k0 + q);
            int nn = colbase + r;
            cp16(buf + ARRB + r * ROWB + q * 2, Wh + (size_t)nn * K + k0 + q);
            cp16(buf + 2 * ARRB + r * ROWB + q * 2, Wl + (size_t)nn * K + k0 + q);
        }
        asm volatile("cp.async.commit_group;");
    };

    const int a_rsel = lane & 15;
    const int a_ksel = (lane >> 4) * 8;
    const int b_nsel = (lane & 7) + ((lane >> 4) << 3);
    const int b_koff = ((lane >> 3) & 1) * 8;

    auto compute = [&](int b) {
        uint32_t sa = sbase + b * BUFB;
        uint32_t sbh = sa + ARRB;
        uint32_t sbl = sa + 2 * ARRB;
        #pragma unroll
        for (int ks = 0; ks < KC; ks += 16) {
            uint32_t ah[2][4], as[2][4];
            #pragma unroll
            for (int mt = 0; mt < 2; mt++) {
                uint32_t addr = sa + (m_off + mt * 16 + a_rsel) * ROWB + (ks + a_ksel) * 2;
                ldsm4(ah[mt], addr);
                #pragma unroll
                for (int q = 0; q < 4; q++) {
                    __half2 h = __hmul2(*(__half2*)&ah[mt][q], inv512);
                    as[mt][q] = *(uint32_t*)&h;
                }
            }
            #pragma unroll
            for (int p = 0; p < 4; p++) {
                uint32_t off = (n_off + p * 16 + b_nsel) * ROWB + (ks + b_koff) * 2;
                uint32_t bh4[4], bl4[4];
                ldsm4(bh4, sbh + off);
                ldsm4(bl4, sbl + off);
                #pragma unroll
                for (int mt = 0; mt < 2; mt++) {
                    mma_f16(acc[mt][2 * p],     ah[mt], bh4[0], bh4[1]);
                    mma_f16(acc[mt][2 * p + 1], ah[mt], bh4[2], bh4[3]);
                }
                #pragma unroll
                for (int mt = 0; mt < 2; mt++) {
                    mma_f16(acc[mt][2 * p],     as[mt], bl4[0], bl4[1]);
                    mma_f16(acc[mt][2 * p + 1], as[mt], bl4[2], bl4[3]);
                }
            }
        }
    };

    stage(0, 0);
    asm volatile("cp.async.wait_group 0;");
    __syncthreads();
    for (int c = 0; c < CHUNKS; c++) {
        if (c + 1 < CHUNKS) stage(c + 1, (c + 1) & 1);
        compute(c & 1);
        if (c + 1 < CHUNKS) asm volatile("cp.async.wait_group 0;");
        __syncthreads();
    }

    #pragma unroll
    for (int mt = 0; mt < 2; mt++) {
        int row = row0 + m_off + mt * 16 + (lane >> 2);
        #pragma unroll
        for (int nt = 0; nt < 8; nt++) {
            int col = colbase + n_off + nt * 8 + (lane & 3) * 2;
            float b0 = bias[col], b1 = bias[col + 1];
            float ox0 = acc[mt][nt][0] + b0, oy0 = acc[mt][nt][1] + b1;
            float ox1 = acc[mt][nt][2] + b0, oy1 = acc[mt][nt][3] + b1;
            ox0 = ox0 > 0.f ? ox0 : 0.f; oy0 = oy0 > 0.f ? oy0 : 0.f;
            ox1 = ox1 > 0.f ? ox1 : 0.f; oy1 = oy1 > 0.f ? oy1 : 0.f;
            if (row < M)
                *(__half2*)(C16 + (size_t)row * 256 + col) = __floats2half2_rn(ox0, oy0);
            if (row + 8 < M)
                *(__half2*)(C16 + (size_t)(row + 8) * 256 + col) = __floats2half2_rn(ox1, oy1);
        }
    }
}

// ---------------- pooling + heads ----------------
__device__ __forceinline__ int lower_bound_i(const int* __restrict__ a, int n, int key) {
    int lo = 0, hi = n;
    while (lo < hi) {
        int mid = (lo + hi) >> 1;
        if (a[mid] < key) lo = mid + 1; else hi = mid;
    }
    return lo;
}
__global__ __launch_bounds__(256)
void pool_heads_kernel(const __half* __restrict__ h, const int* __restrict__ batch,
                       const float* __restrict__ Wmu, const float* __restrict__ bmu,
                       const float* __restrict__ Wlv, const float* __restrict__ blv,
                       float* __restrict__ out, int n, int g_total) {
    int g = blockIdx.x;
    __shared__ float hg[256];
    int lo = lower_bound_i(batch, n, g);
    int hi = lower_bound_i(batch, n, g + 1);
    int tid = threadIdx.x;
    float s = 0.f;
    for (int i = lo; i < hi; i++) s += __half2float(h[(size_t)i * 256 + tid]);
    float cnt = (float)(hi - lo);
    hg[tid] = s / fmaxf(cnt, 1.0f);
    __syncthreads();
    if (tid < 64) {
        float m = bmu[tid];
        #pragma unroll 8
        for (int k = 0; k < 256; k++) m = fmaf(hg[k], Wmu[k * 64 + tid], m);
        out[g * 64 + tid] = m;
    } else if (tid < 128) {
        int t = tid - 64;
        float m = blv[t];
        #pragma unroll 8
        for (int k = 0; k < 256; k++) m = fmaf(hg[k], Wlv[k * 64 + t], m);
        out[(size_t)g_total * 64 + g * 64 + t] = m;
    }
}

// ---------------- launch ----------------
extern "C" void kernel_launch(void* const* d_in, const int* in_sizes, int n_in,
                              void* d_out, int out_size) {
    const float* x     = (const float*)d_in[0];
    const int*   ei    = (const int*)d_in[1];
    const int*   batch = (const int*)d_in[2];
    int wi = (n_in >= 12) ? 4 : 3;
    const float* W1  = (const float*)d_in[wi + 0];
    const float* b1  = (const float*)d_in[wi + 1];
    const float* W2  = (const float*)d_in[wi + 2];
    const float* b2  = (const float*)d_in[wi + 3];
    const float* Wmu = (const float*)d_in[wi + 4];
    const float* bmu = (const float*)d_in[wi + 5];
    const float* Wlv = (const float*)d_in[wi + 6];
    const float* blv = (const float*)d_in[wi + 7];
    float* out = (float*)d_out;

    int n = in_sizes[0] / 128;
    int e = in_sizes[1] / 2;
    int g = out_size / 128;

    static __half* p_x16 = nullptr;
    static __half* p_a16 = nullptr;
    static __half* p_h16 = nullptr;
    static __half* p_w1h = nullptr; static __half* p_w1l = nullptr;
    static __half* p_w2h = nullptr; static __half* p_w2l = nullptr;
    if (!p_x16) {
        cudaGetSymbolAddress((void**)&p_x16, g_x16);
        cudaGetSymbolAddress((void**)&p_a16, g_a16);
        cudaGetSymbolAddress((void**)&p_h16, g_h16);
        cudaGetSymbolAddress((void**)&p_w1h, g_W1h);
        cudaGetSymbolAddress((void**)&p_w1l, g_W1l);
        cudaGetSymbolAddress((void**)&p_w2h, g_W2h);
        cudaGetSymbolAddress((void**)&p_w2l, g_W2l);
        cudaFuncSetAttribute(gemm_f16<128>, cudaFuncAttributeMaxDynamicSharedMemorySize, GEMM_SMEM);
        cudaFuncSetAttribute(gemm_f16<256>, cudaFuncAttributeMaxDynamicSharedMemorySize, GEMM_SMEM);
    }

    int setup_elems = n * 32;
    if (setup_elems < 256 * 256) setup_elems = 256 * 256;

    setup_kernel<<<(setup_elems + 255) / 256, 256>>>(x, W1, W2, p_w1h, p_w1l, p_w2h, p_w2l, p_x16, n);
    if ((e & 7) == 0) fill8_kernel<<<(e / 8 + 255) / 256, 256>>>(ei, e);
    else              fill1_kernel<<<(e + 255) / 256, 256>>>(ei, e);
    dinv_kernel<<<(n + 255) / 256, 256>>>(n);

    agg_f16_kernel<128><<<(n + 7) / 8, 256>>>(p_x16, p_a16, n);
    gemm_f16<128><<<dim3((n + 127) / 128, 2), 256, GEMM_SMEM>>>(p_a16, p_w1h, p_w1l, b1, p_h16, n);
    agg_f16_kernel<256><<<(n + 7) / 8, 256>>>(p_h16, p_a16, n);
    gemm_f16<256><<<dim3((n + 127) / 128, 2), 256, GEMM_SMEM>>>(p_a16, p_w2h, p_w2l, b2, p_h16, n);
    pool_heads_kernel<<<g, 256>>>(p_h16, batch, Wmu, bmu, Wlv, blv, out, n, g);
}

// round 15
// speedup vs baseline: 1.0058x; 1.0058x over previous
#include <cuda_runtime.h>
#include <cuda_bf16.h>
#include <cuda_fp16.h>
#include <stdint.h>

#define MAX_N 50000
#define MAX_E 800000
#define SLOTS 96          // fixed bucket capacity; deg ~ Poisson(16), P(>96) ~ 0

// ---------------- scratch ----------------
__device__ int   g_cnt[MAX_N];
__device__ int   g_slot[(size_t)MAX_N * SLOTS];
__device__ float g_dinv[MAX_N];
__device__ __align__(16) __half g_x16[(size_t)MAX_N * 128];
__device__ __align__(16) __half g_a16[(size_t)MAX_N * 256];
__device__ __align__(16) __half g_h16[(size_t)MAX_N * 256];
// fp16 weights, transposed [n][k]; Wl pre-scaled by 512 (subnormal-safe)
__device__ __half g_W1h[256 * 128];
__device__ __half g_W1l[256 * 128];
__device__ __half g_W2h[256 * 256];
__device__ __half g_W2l[256 * 256];

// ---------------- chain A: zero counts ----------------
__global__ void zero_cnt_kernel(int n) {
    int i = blockIdx.x * blockDim.x + threadIdx.x;
    if (i < n) g_cnt[i] = 0;
}

// ---------------- chain B: weight split + x->fp16 ----------------
__global__ void prep_kernel(const float* __restrict__ x,
                            const float* __restrict__ W1, const float* __restrict__ W2,
                            __half* __restrict__ W1h, __half* __restrict__ W1l,
                            __half* __restrict__ W2h, __half* __restrict__ W2l,
                            __half* __restrict__ x16, int n) {
    int i = blockIdx.x * blockDim.x + threadIdx.x;
    if (i < 256 * 128) {
        int nn = i >> 7, k = i & 127;
        float w = W1[k * 256 + nn];
        __half h = __float2half_rn(w);
        W1h[i] = h;
        W1l[i] = __float2half_rn((w - __half2float(h)) * 512.0f);
    }
    if (i < 256 * 256) {
        int nn = i >> 8, k = i & 255;
        float w = W2[k * 256 + nn];
        __half h = __float2half_rn(w);
        W2h[i] = h;
        W2l[i] = __float2half_rn((w - __half2float(h)) * 512.0f);
    }
    if (i < n * 32) {
        float4 v = ((const float4*)x)[i];
        uint2 o;
        __half2 p0 = __floats2half2_rn(v.x, v.y);
        __half2 p1 = __floats2half2_rn(v.z, v.w);
        o.x = *(uint32_t*)&p0;
        o.y = *(uint32_t*)&p1;
        ((uint2*)x16)[i] = o;
    }
}

// ---------------- single-pass bucket CSR build (count + scatter) ----------
__global__ void fill8_kernel(const int* __restrict__ ei, int e) {
    int i = (blockIdx.x * blockDim.x + threadIdx.x) * 8;
    if (i + 7 < e) {
        int4 s0 = *(const int4*)(ei + i);
        int4 s1 = *(const int4*)(ei + i + 4);
        int4 d0 = *(const int4*)(ei + e + i);
        int4 d1 = *(const int4*)(ei + e + i + 4);
        int p0 = atomicAdd(&g_cnt[d0.x], 1);
        int p1 = atomicAdd(&g_cnt[d0.y], 1);
        int p2 = atomicAdd(&g_cnt[d0.z], 1);
        int p3 = atomicAdd(&g_cnt[d0.w], 1);
        int p4 = atomicAdd(&g_cnt[d1.x], 1);
        int p5 = atomicAdd(&g_cnt[d1.y], 1);
        int p6 = atomicAdd(&g_cnt[d1.z], 1);
        int p7 = atomicAdd(&g_cnt[d1.w], 1);
        if (p0 < SLOTS) g_slot[(size_t)d0.x * SLOTS + p0] = s0.x;
        if (p1 < SLOTS) g_slot[(size_t)d0.y * SLOTS + p1] = s0.y;
        if (p2 < SLOTS) g_slot[(size_t)d0.z * SLOTS + p2] = s0.z;
        if (p3 < SLOTS) g_slot[(size_t)d0.w * SLOTS + p3] = s0.w;
        if (p4 < SLOTS) g_slot[(size_t)d1.x * SLOTS + p4] = s1.x;
        if (p5 < SLOTS) g_slot[(size_t)d1.y * SLOTS + p5] = s1.y;
        if (p6 < SLOTS) g_slot[(size_t)d1.z * SLOTS + p6] = s1.z;
        if (p7 < SLOTS) g_slot[(size_t)d1.w * SLOTS + p7] = s1.w;
    } else {
        for (int j = i; j < e; j++) {
            int src = ei[j];
            int d = ei[e + j];
            int pos = atomicAdd(&g_cnt[d], 1);
            if (pos < SLOTS) g_slot[(size_t)d * SLOTS + pos] = src;
        }
    }
}
__global__ void fill1_kernel(const int* __restrict__ ei, int e) {
    int i = blockIdx.x * blockDim.x + threadIdx.x;
    if (i < e) {
        int src = ei[i];
        int d = ei[e + i];
        int pos = atomicAdd(&g_cnt[d], 1);
        if (pos < SLOTS) g_slot[(size_t)d * SLOTS + pos] = src;
    }
}

// dinv from final counts
__global__ void dinv_kernel(int n) {
    int i = blockIdx.x * blockDim.x + threadIdx.x;
    if (i < n) g_dinv[i] = rsqrtf((float)(g_cnt[i] + 1));
}

// ---------------- fp16 aggregation: warp-per-node, shfl-preloaded slots ----
// (R13 proven version: fp32 accumulation, unroll-4 gather)
template <int F>
__global__ void agg_f16_kernel(const __half* __restrict__ xh, __half* __restrict__ out, int n) {
    int warp = blockIdx.x * (blockDim.x >> 5) + (threadIdx.x >> 5);
    int lane = threadIdx.x & 31;
    if (warp >= n) return;
    constexpr int VH = F / 32;
    constexpr int V2 = VH / 2;
    float di = g_dinv[warp];
    float acc[VH];
    const uint32_t* __restrict__ xw = (const uint32_t*)xh;
    #pragma unroll
    for (int v = 0; v < V2; v++) {
        uint32_t u = xw[(size_t)warp * (F / 2) + lane * V2 + v];
        float2 t = __half22float2(*(__half2*)&u);
        acc[2 * v] = di * t.x;
        acc[2 * v + 1] = di * t.y;
    }

    int deg = g_cnt[warp];
    if (deg > SLOTS) deg = SLOTS;
    const int* __restrict__ sl = g_slot + (size_t)warp * SLOTS;

    int pslot = (lane < deg) ? sl[lane] : 0;
    float pdinv = (lane < deg) ? g_dinv[pslot] : 0.f;

    auto ldrow = [&](uint32_t* u, int s) {
        if constexpr (V2 == 4) {
            uint4 a = *(const uint4*)(xw + (size_t)s * (F / 2) + lane * 4);
            u[0] = a.x; u[1] = a.y; u[2] = a.z; u[3] = a.w;
        } else {
            uint2 a = *(const uint2*)(xw + (size_t)s * (F / 2) + lane * 2);
            u[0] = a.x; u[1] = a.y;
        }
    };
    auto accum = [&](const uint32_t* u, float w) {
        #pragma unroll
        for (int v = 0; v < V2; v++) {
            float2 t = __half22float2(*(const __half2*)&u[v]);
            acc[2 * v]     = fmaf(w, t.x, acc[2 * v]);
            acc[2 * v + 1] = fmaf(w, t.y, acc[2 * v + 1]);
        }
    };

    int dfast = deg < 32 ? deg : 32;
    int e = 0;
    for (; e + 3 < dfast; e += 4) {
        int s0 = __shfl_sync(0xffffffffu, pslot, e);
        int s1 = __shfl_sync(0xffffffffu, pslot, e + 1);
        int s2 = __shfl_sync(0xffffffffu, pslot, e + 2);
        int s3 = __shfl_sync(0xffffffffu, pslot, e + 3);
        float w0 = __shfl_sync(0xffffffffu, pdinv, e);
        float w1 = __shfl_sync(0xffffffffu, pdinv, e + 1);
        float w2 = __shfl_sync(0xffffffffu, pdinv, e + 2);
        float w3 = __shfl_sync(0xffffffffu, pdinv, e + 3);
        uint32_t u0[V2], u1[V2], u2[V2], u3[V2];
        ldrow(u0, s0); ldrow(u1, s1); ldrow(u2, s2); ldrow(u3, s3);
        accum(u0, w0); accum(u1, w1); accum(u2, w2); accum(u3, w3);
    }
    for (; e < dfast; e++) {
        int s = __shfl_sync(0xffffffffu, pslot, e);
        float w = __shfl_sync(0xffffffffu, pdinv, e);
        uint32_t u[V2];
        ldrow(u, s);
        accum(u, w);
    }
    for (; e < deg; e++) {            // rare tail: deg > 32
        int s = sl[e];
        float w = g_dinv[s];
        uint32_t u[V2];
        ldrow(u, s);
        accum(u, w);
    }

    __half2* op = (__half2*)(out + (size_t)warp * F + lane * VH);
    #pragma unroll
    for (int v = 0; v < V2; v++)
        op[v] = __floats2half2_rn(di * acc[2 * v], di * acc[2 * v + 1]);
}

// ---------------- fp16 tensor GEMM: ldmatrix + cp.async, KC=64 ------------
__device__ __forceinline__ void mma_f16(float* c, const uint32_t* a, uint32_t b0, uint32_t b1) {
    asm volatile(
        "mma.sync.aligned.m16n8k16.row.col.f32.f16.f16.f32 "
        "{%0,%1,%2,%3}, {%4,%5,%6,%7}, {%8,%9}, {%0,%1,%2,%3};"
        : "+f"(c[0]), "+f"(c[1]), "+f"(c[2]), "+f"(c[3])
        : "r"(a[0]), "r"(a[1]), "r"(a[2]), "r"(a[3]), "r"(b0), "r"(b1));
}
__device__ __forceinline__ void ldsm4(uint32_t* r, uint32_t addr) {
    asm volatile("ldmatrix.sync.aligned.m8n8.x4.shared.b16 {%0,%1,%2,%3}, [%4];"
                 : "=r"(r[0]), "=r"(r[1]), "=r"(r[2]), "=r"(r[3]) : "r"(addr));
}
__device__ __forceinline__ void cp16(uint32_t dst, const void* src) {
    asm volatile("cp.async.cg.shared.global [%0], [%1], 16;" :: "r"(dst), "l"(src));
}
__device__ __forceinline__ uint32_t smem_u32(const void* p) {
    uint32_t a;
    asm("{.reg .u64 t; cvta.to.shared.u64 t, %1; cvt.u32.u64 %0, t;}" : "=r"(a) : "l"(p));
    return a;
}

#define KC 64
#define ROWB 144
#define ARRB (128 * ROWB)
#define BUFB (3 * ARRB)
#define GEMM_SMEM (2 * BUFB)

template <int K>
__global__ __launch_bounds__(256, 2)
void gemm_f16(const __half* __restrict__ A, const __half* __restrict__ Wh,
              const __half* __restrict__ Wl, const float* __restrict__ bias,
              __half* __restrict__ C16, int M) {
    extern __shared__ __half smem[];
    const uint32_t sbase = smem_u32(smem);
    const int tid = threadIdx.x;
    const int wid = tid >> 5;
    const int lane = tid & 31;
    const int row0 = blockIdx.x * 128;
    const int colbase = blockIdx.y * 128;
    const int m_off = (wid & 3) * 32;
    const int n_off = (wid >> 2) * 64;
    const __half2 inv512 = __half2half2(__float2half(0.001953125f));
    constexpr int CHUNKS = K / KC;

    float acc[2][8][4];
    #pragma unroll
    for (int mt = 0; mt < 2; mt++)
        #pragma unroll
        for (int nt = 0; nt < 8; nt++)
            #pragma unroll
            for (int q = 0; q < 4; q++) acc[mt][nt][q] = 0.f;

    auto stage = [&](int c, int b) {
        int k0 = c * KC;
        uint32_t buf = sbase + b * BUFB;
        #pragma unroll
        for (int it = 0; it < 4; it++) {
            int i = tid + it * 256;
            int r = i >> 3;
            int q = (i & 7) * 8;
            int rr = row0 + r; if (rr >= M) rr = M - 1;
            cp16(buf + r * ROWB + q * 2, A + (size_t)rr * K + k0 + q);
            int nn = colbase + r;
            cp16(buf + ARRB + r * ROWB + q * 2, Wh + (size_t)nn * K + k0 + q);
            cp16(buf + 2 * ARRB + r * ROWB + q * 2, Wl + (size_t)nn * K + k0 + q);
        }
        asm volatile("cp.async.commit_group;");
    };

    const int a_rsel = lane & 15;
    const int a_ksel = (lane >> 4) * 8;
    const int b_nsel = (lane & 7) + ((lane >> 4) << 3);
    const int b_koff = ((lane >> 3) & 1) * 8;

    auto compute = [&](int b) {
        uint32_t sa = sbase + b * BUFB;
        uint32_t sbh = sa + ARRB;
        uint32_t sbl = sa + 2 * ARRB;
        #pragma unroll
        for (int ks = 0; ks < KC; ks += 16) {
            uint32_t ah[2][4], as[2][4];
            #pragma unroll
            for (int mt = 0; mt < 2; mt++) {
                uint32_t addr = sa + (m_off + mt * 16 + a_rsel) * ROWB + (ks + a_ksel) * 2;
                ldsm4(ah[mt], addr);
                #pragma unroll
                for (int q = 0; q < 4; q++) {
                    __half2 h = __hmul2(*(__half2*)&ah[mt][q], inv512);
                    as[mt][q] = *(uint32_t*)&h;
                }
            }
            #pragma unroll
            for (int p = 0; p < 4; p++) {
                uint32_t off = (n_off + p * 16 + b_nsel) * ROWB + (ks + b_koff) * 2;
                uint32_t bh4[4], bl4[4];
                ldsm4(bh4, sbh + off);
                ldsm4(bl4, sbl + off);
                #pragma unroll
                for (int mt = 0; mt < 2; mt++) {
                    mma_f16(acc[mt][2 * p],     ah[mt], bh4[0], bh4[1]);
                    mma_f16(acc[mt][2 * p + 1], ah[mt], bh4[2], bh4[3]);
                }
                #pragma unroll
                for (int mt = 0; mt < 2; mt++) {
                    mma_f16(acc[mt][2 * p],     as[mt], bl4[0], bl4[1]);
                    mma_f16(acc[mt][2 * p + 1], as[mt], bl4[2], bl4[3]);
                }
            }
        }
    };

    stage(0, 0);
    asm volatile("cp.async.wait_group 0;");
    __syncthreads();
    for (int c = 0; c < CHUNKS; c++) {
        if (c + 1 < CHUNKS) stage(c + 1, (c + 1) & 1);
        compute(c & 1);
        if (c + 1 < CHUNKS) asm volatile("cp.async.wait_group 0;");
        __syncthreads();
    }

    #pragma unroll
    for (int mt = 0; mt < 2; mt++) {
        int row = row0 + m_off + mt * 16 + (lane >> 2);
        #pragma unroll
        for (int nt = 0; nt < 8; nt++) {
            int col = colbase + n_off + nt * 8 + (lane & 3) * 2;
            float b0 = bias[col], b1 = bias[col + 1];
            float ox0 = acc[mt][nt][0] + b0, oy0 = acc[mt][nt][1] + b1;
            float ox1 = acc[mt][nt][2] + b0, oy1 = acc[mt][nt][3] + b1;
            ox0 = ox0 > 0.f ? ox0 : 0.f; oy0 = oy0 > 0.f ? oy0 : 0.f;
            ox1 = ox1 > 0.f ? ox1 : 0.f; oy1 = oy1 > 0.f ? oy1 : 0.f;
            if (row < M)
                *(__half2*)(C16 + (size_t)row * 256 + col) = __floats2half2_rn(ox0, oy0);
            if (row + 8 < M)
                *(__half2*)(C16 + (size_t)(row + 8) * 256 + col) = __floats2half2_rn(ox1, oy1);
        }
    }
}

// ---------------- pooling + heads ----------------
__device__ __forceinline__ int lower_bound_i(const int* __restrict__ a, int n, int key) {
    int lo = 0, hi = n;
    while (lo < hi) {
        int mid = (lo + hi) >> 1;
        if (a[mid] < key) lo = mid + 1; else hi = mid;
    }
    return lo;
}
__global__ __launch_bounds__(256)
void pool_heads_kernel(const __half* __restrict__ h, const int* __restrict__ batch,
                       const float* __restrict__ Wmu, const float* __restrict__ bmu,
                       const float* __restrict__ Wlv, const float* __restrict__ blv,
                       float* __restrict__ out, int n, int g_total) {
    int g = blockIdx.x;
    __shared__ float hg[256];
    int lo = lower_bound_i(batch, n, g);
    int hi = lower_bound_i(batch, n, g + 1);
    int tid = threadIdx.x;
    float s = 0.f;
    for (int i = lo; i < hi; i++) s += __half2float(h[(size_t)i * 256 + tid]);
    float cnt = (float)(hi - lo);
    hg[tid] = s / fmaxf(cnt, 1.0f);
    __syncthreads();
    if (tid < 64) {
        float m = bmu[tid];
        #pragma unroll 8
        for (int k = 0; k < 256; k++) m = fmaf(hg[k], Wmu[k * 64 + tid], m);
        out[g * 64 + tid] = m;
    } else if (tid < 128) {
        int t = tid - 64;
        float m = blv[t];
        #pragma unroll 8
        for (int k = 0; k < 256; k++) m = fmaf(hg[k], Wlv[k * 64 + t], m);
        out[(size_t)g_total * 64 + g * 64 + t] = m;
    }
}

// ---------------- launch ----------------
extern "C" void kernel_launch(void* const* d_in, const int* in_sizes, int n_in,
                              void* d_out, int out_size) {
    const float* x     = (const float*)d_in[0];
    const int*   ei    = (const int*)d_in[1];
    const int*   batch = (const int*)d_in[2];
    int wi = (n_in >= 12) ? 4 : 3;
    const float* W1  = (const float*)d_in[wi + 0];
    const float* b1  = (const float*)d_in[wi + 1];
    const float* W2  = (const float*)d_in[wi + 2];
    const float* b2  = (const float*)d_in[wi + 3];
    const float* Wmu = (const float*)d_in[wi + 4];
    const float* bmu = (const float*)d_in[wi + 5];
    const float* Wlv = (const float*)d_in[wi + 6];
    const float* blv = (const float*)d_in[wi + 7];
    float* out = (float*)d_out;

    int n = in_sizes[0] / 128;
    int e = in_sizes[1] / 2;
    int g = out_size / 128;

    static __half* p_x16 = nullptr;
    static __half* p_a16 = nullptr;
    static __half* p_h16 = nullptr;
    static __half* p_w1h = nullptr; static __half* p_w1l = nullptr;
    static __half* p_w2h = nullptr; static __half* p_w2l = nullptr;
    static cudaStream_t s1 = nullptr;
    static cudaEvent_t evFork = nullptr, evJoin = nullptr;
    if (!p_x16) {
        cudaGetSymbolAddress((void**)&p_x16, g_x16);
        cudaGetSymbolAddress((void**)&p_a16, g_a16);
        cudaGetSymbolAddress((void**)&p_h16, g_h16);
        cudaGetSymbolAddress((void**)&p_w1h, g_W1h);
        cudaGetSymbolAddress((void**)&p_w1l, g_W1l);
        cudaGetSymbolAddress((void**)&p_w2h, g_W2h);
        cudaGetSymbolAddress((void**)&p_w2l, g_W2l);
        cudaFuncSetAttribute(gemm_f16<128>, cudaFuncAttributeMaxDynamicSharedMemorySize, GEMM_SMEM);
        cudaFuncSetAttribute(gemm_f16<256>, cudaFuncAttributeMaxDynamicSharedMemorySize, GEMM_SMEM);
        cudaStreamCreateWithFlags(&s1, cudaStreamNonBlocking);
        cudaEventCreateWithFlags(&evFork, cudaEventDisableTiming);
        cudaEventCreateWithFlags(&evJoin, cudaEventDisableTiming);
    }

    int prep_elems = n * 32;
    if (prep_elems < 256 * 256) prep_elems = 256 * 256;

    // fork: chain B (weights + x->fp16) on s1, chain A (CSR build) on main
    cudaEventRecord(evFork, 0);
    cudaStreamWaitEvent(s1, evFork, 0);
    prep_kernel<<<(prep_elems + 255) / 256, 256, 0, s1>>>(x, W1, W2, p_w1h, p_w1l,
                                                          p_w2h, p_w2l, p_x16, n);
    cudaEventRecord(evJoin, s1);

    zero_cnt_kernel<<<(n + 255) / 256, 256>>>(n);
    if ((e & 7) == 0) fill8_kernel<<<(e / 8 + 255) / 256, 256>>>(ei, e);
    else              fill1_kernel<<<(e + 255) / 256, 256>>>(ei, e);
    dinv_kernel<<<(n + 255) / 256, 256>>>(n);

    // join: agg128 needs x16 (B) and slots/dinv (A)
    cudaStreamWaitEvent(0, evJoin, 0);

    agg_f16_kernel<128><<<(n + 7) / 8, 256>>>(p_x16, p_a16, n);
    gemm_f16<128><<<dim3((n + 127) / 128, 2), 256, GEMM_SMEM>>>(p_a16, p_w1h, p_w1l, b1, p_h16, n);
    agg_f16_kernel<256><<<(n + 7) / 8, 256>>>(p_h16, p_a16, n);
    gemm_f16<256><<<dim3((n + 127) / 128, 2), 256, GEMM_SMEM>>>(p_a16, p_w2h, p_w2l, b2, p_h16, n);
    pool_heads_kernel<<<g, 256>>>(p_h16, batch, Wmu, bmu, Wlv, blv, out, n, g);
}

// round 16
// speedup vs baseline: 1.0146x; 1.0088x over previous
#include <cuda_runtime.h>
#include <cuda_bf16.h>
#include <cuda_fp16.h>
#include <stdint.h>

#define MAX_N 50000
#define MAX_E 800000
#define SLOTS 96          // fixed bucket capacity; deg ~ Poisson(16), P(>96) ~ 0

// ---------------- scratch ----------------
__device__ int   g_cnt[MAX_N];
__device__ int   g_slot[(size_t)MAX_N * SLOTS];
__device__ __align__(16) __half g_x16[(size_t)MAX_N * 128];
__device__ __align__(16) __half g_a16[(size_t)MAX_N * 256];
__device__ __align__(16) __half g_h16[(size_t)MAX_N * 256];
// fp16 weights, transposed [n][k]; Wl pre-scaled by 512 (subnormal-safe)
__device__ __half g_W1h[256 * 128];
__device__ __half g_W1l[256 * 128];
__device__ __half g_W2h[256 * 256];
__device__ __half g_W2l[256 * 256];

// ---------------- chain B: weight split + x->fp16 ----------------
__global__ void prep_kernel(const float* __restrict__ x,
                            const float* __restrict__ W1, const float* __restrict__ W2,
                            __half* __restrict__ W1h, __half* __restrict__ W1l,
                            __half* __restrict__ W2h, __half* __restrict__ W2l,
                            __half* __restrict__ x16, int n) {
    int i = blockIdx.x * blockDim.x + threadIdx.x;
    if (i < 256 * 128) {
        int nn = i >> 7, k = i & 127;
        float w = W1[k * 256 + nn];
        __half h = __float2half_rn(w);
        W1h[i] = h;
        W1l[i] = __float2half_rn((w - __half2float(h)) * 512.0f);
    }
    if (i < 256 * 256) {
        int nn = i >> 8, k = i & 255;
        float w = W2[k * 256 + nn];
        __half h = __float2half_rn(w);
        W2h[i] = h;
        W2l[i] = __float2half_rn((w - __half2float(h)) * 512.0f);
    }
    if (i < n * 32) {
        float4 v = ((const float4*)x)[i];
        uint2 o;
        __half2 p0 = __floats2half2_rn(v.x, v.y);
        __half2 p1 = __floats2half2_rn(v.z, v.w);
        o.x = *(uint32_t*)&p0;
        o.y = *(uint32_t*)&p1;
        ((uint2*)x16)[i] = o;
    }
}

// ---------------- single-pass bucket CSR build (count + scatter) ----------
__global__ void fill8_kernel(const int* __restrict__ ei, int e) {
    int i = (blockIdx.x * blockDim.x + threadIdx.x) * 8;
    if (i + 7 < e) {
        int4 s0 = *(const int4*)(ei + i);
        int4 s1 = *(const int4*)(ei + i + 4);
        int4 d0 = *(const int4*)(ei + e + i);
        int4 d1 = *(const int4*)(ei + e + i + 4);
        int p0 = atomicAdd(&g_cnt[d0.x], 1);
        int p1 = atomicAdd(&g_cnt[d0.y], 1);
        int p2 = atomicAdd(&g_cnt[d0.z], 1);
        int p3 = atomicAdd(&g_cnt[d0.w], 1);
        int p4 = atomicAdd(&g_cnt[d1.x], 1);
        int p5 = atomicAdd(&g_cnt[d1.y], 1);
        int p6 = atomicAdd(&g_cnt[d1.z], 1);
        int p7 = atomicAdd(&g_cnt[d1.w], 1);
        if (p0 < SLOTS) g_slot[(size_t)d0.x * SLOTS + p0] = s0.x;
        if (p1 < SLOTS) g_slot[(size_t)d0.y * SLOTS + p1] = s0.y;
        if (p2 < SLOTS) g_slot[(size_t)d0.z * SLOTS + p2] = s0.z;
        if (p3 < SLOTS) g_slot[(size_t)d0.w * SLOTS + p3] = s0.w;
        if (p4 < SLOTS) g_slot[(size_t)d1.x * SLOTS + p4] = s1.x;
        if (p5 < SLOTS) g_slot[(size_t)d1.y * SLOTS + p5] = s1.y;
        if (p6 < SLOTS) g_slot[(size_t)d1.z * SLOTS + p6] = s1.z;
        if (p7 < SLOTS) g_slot[(size_t)d1.w * SLOTS + p7] = s1.w;
    } else {
        for (int j = i; j < e; j++) {
            int src = ei[j];
            int d = ei[e + j];
            int pos = atomicAdd(&g_cnt[d], 1);
            if (pos < SLOTS) g_slot[(size_t)d * SLOTS + pos] = src;
        }
    }
}
__global__ void fill1_kernel(const int* __restrict__ ei, int e) {
    int i = blockIdx.x * blockDim.x + threadIdx.x;
    if (i < e) {
        int src = ei[i];
        int d = ei[e + i];
        int pos = atomicAdd(&g_cnt[d], 1);
        if (pos < SLOTS) g_slot[(size_t)d * SLOTS + pos] = src;
    }
}

// ---------------- fp16 aggregation: shfl-preload + inline rsqrt dinv ------
// F=128: unroll-8 gather; F=256: unroll-4 (at L2-BW floor already)
template <int F>
__global__ void agg_f16_kernel(const __half* __restrict__ xh, __half* __restrict__ out, int n) {
    int warp = blockIdx.x * (blockDim.x >> 5) + (threadIdx.x >> 5);
    int lane = threadIdx.x & 31;
    if (warp >= n) return;
    constexpr int VH = F / 32;
    constexpr int V2 = VH / 2;
    int cnt_self = g_cnt[warp];
    float di = rsqrtf((float)(cnt_self + 1));
    float acc[VH];
    const uint32_t* __restrict__ xw = (const uint32_t*)xh;
    #pragma unroll
    for (int v = 0; v < V2; v++) {
        uint32_t u = xw[(size_t)warp * (F / 2) + lane * V2 + v];
        float2 t = __half22float2(*(__half2*)&u);
        acc[2 * v] = di * t.x;
        acc[2 * v + 1] = di * t.y;
    }

    int deg = cnt_self;
    if (deg > SLOTS) deg = SLOTS;
    const int* __restrict__ sl = g_slot + (size_t)warp * SLOTS;

    // per-lane preload: slot + inline-computed dinv (deg warp-uniform)
    int pslot = (lane < deg) ? sl[lane] : 0;
    float pdinv = (lane < deg) ? rsqrtf((float)(g_cnt[pslot] + 1)) : 0.f;

    auto ldrow = [&](uint32_t* u, int s) {
        if constexpr (V2 == 4) {
            uint4 a = *(const uint4*)(xw + (size_t)s * (F / 2) + lane * 4);
            u[0] = a.x; u[1] = a.y; u[2] = a.z; u[3] = a.w;
        } else {
            uint2 a = *(const uint2*)(xw + (size_t)s * (F / 2) + lane * 2);
            u[0] = a.x; u[1] = a.y;
        }
    };
    auto accum = [&](const uint32_t* u, float w) {
        #pragma unroll
        for (int v = 0; v < V2; v++) {
            float2 t = __half22float2(*(const __half2*)&u[v]);
            acc[2 * v]     = fmaf(w, t.x, acc[2 * v]);
            acc[2 * v + 1] = fmaf(w, t.y, acc[2 * v + 1]);
        }
    };

    int dfast = deg < 32 ? deg : 32;
    int e = 0;
    if constexpr (V2 == 2) {
        // unroll-8 (MLP=8) for the narrow row case
        for (; e + 7 < dfast; e += 8) {
            int ss[8]; float ww[8];
            #pragma unroll
            for (int j = 0; j < 8; j++) {
                ss[j] = __shfl_sync(0xffffffffu, pslot, e + j);
                ww[j] = __shfl_sync(0xffffffffu, pdinv, e + j);
            }
            uint32_t uu[8][2];
            #pragma unroll
            for (int j = 0; j < 8; j++) ldrow(uu[j], ss[j]);
            #pragma unroll
            for (int j = 0; j < 8; j++) accum(uu[j], ww[j]);
        }
    }
    for (; e + 3 < dfast; e += 4) {
        int s0 = __shfl_sync(0xffffffffu, pslot, e);
        int s1 = __shfl_sync(0xffffffffu, pslot, e + 1);
        int s2 = __shfl_sync(0xffffffffu, pslot, e + 2);
        int s3 = __shfl_sync(0xffffffffu, pslot, e + 3);
        float w0 = __shfl_sync(0xffffffffu, pdinv, e);
        float w1 = __shfl_sync(0xffffffffu, pdinv, e + 1);
        float w2 = __shfl_sync(0xffffffffu, pdinv, e + 2);
        float w3 = __shfl_sync(0xffffffffu, pdinv, e + 3);
        uint32_t u0[V2], u1[V2], u2[V2], u3[V2];
        ldrow(u0, s0); ldrow(u1, s1); ldrow(u2, s2); ldrow(u3, s3);
        accum(u0, w0); accum(u1, w1); accum(u2, w2); accum(u3, w3);
    }
    for (; e < dfast; e++) {
        int s = __shfl_sync(0xffffffffu, pslot, e);
        float w = __shfl_sync(0xffffffffu, pdinv, e);
        uint32_t u[V2];
        ldrow(u, s);
        accum(u, w);
    }
    for (; e < deg; e++) {            // rare tail: deg > 32
        int s = sl[e];
        float w = rsqrtf((float)(g_cnt[s] + 1));
        uint32_t u[V2];
        ldrow(u, s);
        accum(u, w);
    }

    __half2* op = (__half2*)(out + (size_t)warp * F + lane * VH);
    #pragma unroll
    for (int v = 0; v < V2; v++)
        op[v] = __floats2half2_rn(di * acc[2 * v], di * acc[2 * v + 1]);
}

// ---------------- fp16 tensor GEMM: ldmatrix + cp.async, KC=64 ------------
__device__ __forceinline__ void mma_f16(float* c, const uint32_t* a, uint32_t b0, uint32_t b1) {
    asm volatile(
        "mma.sync.aligned.m16n8k16.row.col.f32.f16.f16.f32 "
        "{%0,%1,%2,%3}, {%4,%5,%6,%7}, {%8,%9}, {%0,%1,%2,%3};"
        : "+f"(c[0]), "+f"(c[1]), "+f"(c[2]), "+f"(c[3])
        : "r"(a[0]), "r"(a[1]), "r"(a[2]), "r"(a[3]), "r"(b0), "r"(b1));
}
__device__ __forceinline__ void ldsm4(uint32_t* r, uint32_t addr) {
    asm volatile("ldmatrix.sync.aligned.m8n8.x4.shared.b16 {%0,%1,%2,%3}, [%4];"
                 : "=r"(r[0]), "=r"(r[1]), "=r"(r[2]), "=r"(r[3]) : "r"(addr));
}
__device__ __forceinline__ void cp16(uint32_t dst, const void* src) {
    asm volatile("cp.async.cg.shared.global [%0], [%1], 16;" :: "r"(dst), "l"(src));
}
__device__ __forceinline__ uint32_t smem_u32(const void* p) {
    uint32_t a;
    asm("{.reg .u64 t; cvta.to.shared.u64 t, %1; cvt.u32.u64 %0, t;}" : "=r"(a) : "l"(p));
    return a;
}

#define KC 64
#define ROWB 144
#define ARRB (128 * ROWB)
#define BUFB (3 * ARRB)
#define GEMM_SMEM (2 * BUFB)

template <int K>
__global__ __launch_bounds__(256, 2)
void gemm_f16(const __half* __restrict__ A, const __half* __restrict__ Wh,
              const __half* __restrict__ Wl, const float* __restrict__ bias,
              __half* __restrict__ C16, int M) {
    extern __shared__ __half smem[];
    const uint32_t sbase = smem_u32(smem);
    const int tid = threadIdx.x;
    const int wid = tid >> 5;
    const int lane = tid & 31;
    const int row0 = blockIdx.x * 128;
    const int colbase = blockIdx.y * 128;
    const int m_off = (wid & 3) * 32;
    const int n_off = (wid >> 2) * 64;
    const __half2 inv512 = __half2half2(__float2half(0.001953125f));
    constexpr int CHUNKS = K / KC;

    float acc[2][8][4];
    #pragma unroll
    for (int mt = 0; mt < 2; mt++)
        #pragma unroll
        for (int nt = 0; nt < 8; nt++)
            #pragma unroll
            for (int q = 0; q < 4; q++) acc[mt][nt][q] = 0.f;

    auto stage = [&](int c, int b) {
        int k0 = c * KC;
        uint32_t buf = sbase + b * BUFB;
        #pragma unroll
        for (int it = 0; it < 4; it++) {
            int i = tid + it * 256;
            int r = i >> 3;
            int q = (i & 7) * 8;
            int rr = row0 + r; if (rr >= M) rr = M - 1;
            cp16(buf + r * ROWB + q * 2, A + (size_t)rr * K + k0 + q);
            int nn = colbase + r;
            cp16(buf + ARRB + r * ROWB + q * 2, Wh + (size_t)nn * K + k0 + q);
            cp16(buf + 2 * ARRB + r * ROWB + q * 2, Wl + (size_t)nn * K + k0 + q);
        }
        asm volatile("cp.async.commit_group;");
    };

    const int a_rsel = lane & 15;
    const int a_ksel = (lane >> 4) * 8;
    const int b_nsel = (lane & 7) + ((lane >> 4) << 3);
    const int b_koff = ((lane >> 3) & 1) * 8;

    auto compute = [&](int b) {
        uint32_t sa = sbase + b * BUFB;
        uint32_t sbh = sa + ARRB;
        uint32_t sbl = sa + 2 * ARRB;
        #pragma unroll
        for (int ks = 0; ks < KC; ks += 16) {
            uint32_t ah[2][4], as[2][4];
            #pragma unroll
            for (int mt = 0; mt < 2; mt++) {
                uint32_t addr = sa + (m_off + mt * 16 + a_rsel) * ROWB + (ks + a_ksel) * 2;
                ldsm4(ah[mt], addr);
                #pragma unroll
                for (int q = 0; q < 4; q++) {
                    __half2 h = __hmul2(*(__half2*)&ah[mt][q], inv512);
                    as[mt][q] = *(uint32_t*)&h;
                }
            }
            #pragma unroll
            for (int p = 0; p < 4; p++) {
                uint32_t off = (n_off + p * 16 + b_nsel) * ROWB + (ks + b_koff) * 2;
                uint32_t bh4[4], bl4[4];
                ldsm4(bh4, sbh + off);
                ldsm4(bl4, sbl + off);
                #pragma unroll
                for (int mt = 0; mt < 2; mt++) {
                    mma_f16(acc[mt][2 * p],     ah[mt], bh4[0], bh4[1]);
                    mma_f16(acc[mt][2 * p + 1], ah[mt], bh4[2], bh4[3]);
                }
                #pragma unroll
                for (int mt = 0; mt < 2; mt++) {
                    mma_f16(acc[mt][2 * p],     as[mt], bl4[0], bl4[1]);
                    mma_f16(acc[mt][2 * p + 1], as[mt], bl4[2], bl4[3]);
                }
            }
        }
    };

    stage(0, 0);
    asm volatile("cp.async.wait_group 0;");
    __syncthreads();
    for (int c = 0; c < CHUNKS; c++) {
        if (c + 1 < CHUNKS) stage(c + 1, (c + 1) & 1);
        compute(c & 1);
        if (c + 1 < CHUNKS) asm volatile("cp.async.wait_group 0;");
        __syncthreads();
    }

    #pragma unroll
    for (int mt = 0; mt < 2; mt++) {
        int row = row0 + m_off + mt * 16 + (lane >> 2);
        #pragma unroll
        for (int nt = 0; nt < 8; nt++) {
            int col = colbase + n_off + nt * 8 + (lane & 3) * 2;
            float b0 = bias[col], b1 = bias[col + 1];
            float ox0 = acc[mt][nt][0] + b0, oy0 = acc[mt][nt][1] + b1;
            float ox1 = acc[mt][nt][2] + b0, oy1 = acc[mt][nt][3] + b1;
            ox0 = ox0 > 0.f ? ox0 : 0.f; oy0 = oy0 > 0.f ? oy0 : 0.f;
            ox1 = ox1 > 0.f ? ox1 : 0.f; oy1 = oy1 > 0.f ? oy1 : 0.f;
            if (row < M)
                *(__half2*)(C16 + (size_t)row * 256 + col) = __floats2half2_rn(ox0, oy0);
            if (row + 8 < M)
                *(__half2*)(C16 + (size_t)(row + 8) * 256 + col) = __floats2half2_rn(ox1, oy1);
        }
    }
}

// ---------------- pooling + heads ----------------
__device__ __forceinline__ int lower_bound_i(const int* __restrict__ a, int n, int key) {
    int lo = 0, hi = n;
    while (lo < hi) {
        int mid = (lo + hi) >> 1;
        if (a[mid] < key) lo = mid + 1; else hi = mid;
    }
    return lo;
}
__global__ __launch_bounds__(256)
void pool_heads_kernel(const __half* __restrict__ h, const int* __restrict__ batch,
                       const float* __restrict__ Wmu, const float* __restrict__ bmu,
                       const float* __restrict__ Wlv, const float* __restrict__ blv,
                       float* __restrict__ out, int n, int g_total) {
    int g = blockIdx.x;
    __shared__ float hg[256];
    int lo = lower_bound_i(batch, n, g);
    int hi = lower_bound_i(batch, n, g + 1);
    int tid = threadIdx.x;
    float s = 0.f;
    for (int i = lo; i < hi; i++) s += __half2float(h[(size_t)i * 256 + tid]);
    float cnt = (float)(hi - lo);
    hg[tid] = s / fmaxf(cnt, 1.0f);
    __syncthreads();
    if (tid < 64) {
        float m = bmu[tid];
        #pragma unroll 8
        for (int k = 0; k < 256; k++) m = fmaf(hg[k], Wmu[k * 64 + tid], m);
        out[g * 64 + tid] = m;
    } else if (tid < 128) {
        int t = tid - 64;
        float m = blv[t];
        #pragma unroll 8
        for (int k = 0; k < 256; k++) m = fmaf(hg[k], Wlv[k * 64 + t], m);
        out[(size_t)g_total * 64 + g * 64 + t] = m;
    }
}

// ---------------- launch ----------------
extern "C" void kernel_launch(void* const* d_in, const int* in_sizes, int n_in,
                              void* d_out, int out_size) {
    const float* x     = (const float*)d_in[0];
    const int*   ei    = (const int*)d_in[1];
    const int*   batch = (const int*)d_in[2];
    int wi = (n_in >= 12) ? 4 : 3;
    const float* W1  = (const float*)d_in[wi + 0];
    const float* b1  = (const float*)d_in[wi + 1];
    const float* W2  = (const float*)d_in[wi + 2];
    const float* b2  = (const float*)d_in[wi + 3];
    const float* Wmu = (const float*)d_in[wi + 4];
    const float* bmu = (const float*)d_in[wi + 5];
    const float* Wlv = (const float*)d_in[wi + 6];
    const float* blv = (const float*)d_in[wi + 7];
    float* out = (float*)d_out;

    int n = in_sizes[0] / 128;
    int e = in_sizes[1] / 2;
    int g = out_size / 128;

    static int* p_cnt = nullptr;
    static __half* p_x16 = nullptr;
    static __half* p_a16 = nullptr;
    static __half* p_h16 = nullptr;
    static __half* p_w1h = nullptr; static __half* p_w1l = nullptr;
    static __half* p_w2h = nullptr; static __half* p_w2l = nullptr;
    static cudaStream_t s1 = nullptr;
    static cudaEvent_t evFork = nullptr, evJoin = nullptr;
    if (!p_x16) {
        cudaGetSymbolAddress((void**)&p_cnt, g_cnt);
        cudaGetSymbolAddress((void**)&p_x16, g_x16);
        cudaGetSymbolAddress((void**)&p_a16, g_a16);
        cudaGetSymbolAddress((void**)&p_h16, g_h16);
        cudaGetSymbolAddress((void**)&p_w1h, g_W1h);
        cudaGetSymbolAddress((void**)&p_w1l, g_W1l);
        cudaGetSymbolAddress((void**)&p_w2h, g_W2h);
        cudaGetSymbolAddress((void**)&p_w2l, g_W2l);
        cudaFuncSetAttribute(gemm_f16<128>, cudaFuncAttributeMaxDynamicSharedMemorySize, GEMM_SMEM);
        cudaFuncSetAttribute(gemm_f16<256>, cudaFuncAttributeMaxDynamicSharedMemorySize, GEMM_SMEM);
        cudaStreamCreateWithFlags(&s1, cudaStreamNonBlocking);
        cudaEventCreateWithFlags(&evFork, cudaEventDisableTiming);
        cudaEventCreateWithFlags(&evJoin, cudaEventDisableTiming);
    }

    int prep_elems = n * 32;
    if (prep_elems < 256 * 256) prep_elems = 256 * 256;

    // fork: chain B (weights + x->fp16) on s1, chain A (CSR build) on main
    cudaEventRecord(evFork, 0);
    cudaStreamWaitEvent(s1, evFork, 0);
    prep_kernel<<<(prep_elems + 255) / 256, 256, 0, s1>>>(x, W1, W2, p_w1h, p_w1l,
                                                          p_w2h, p_w2l, p_x16, n);
    cudaEventRecord(evJoin, s1);

    cudaMemsetAsync(p_cnt, 0, (size_t)n * sizeof(int), 0);
    if ((e & 7) == 0) fill8_kernel<<<(e / 8 + 255) / 256, 256>>>(ei, e);
    else              fill1_kernel<<<(e + 255) / 256, 256>>>(ei, e);

    // join: agg128 needs x16 (B) and slots/cnt (A)
    cudaStreamWaitEvent(0, evJoin, 0);

    agg_f16_kernel<128><<<(n + 7) / 8, 256>>>(p_x16, p_a16, n);
    gemm_f16<128><<<dim3((n + 127) / 128, 2), 256, GEMM_SMEM>>>(p_a16, p_w1h, p_w1l, b1, p_h16, n);
    agg_f16_kernel<256><<<(n + 7) / 8, 256>>>(p_h16, p_a16, n);
    gemm_f16<256><<<dim3((n + 127) / 128, 2), 256, GEMM_SMEM>>>(p_a16, p_w2h, p_w2l, b2, p_h16, n);
    pool_heads_kernel<<<g, 256>>>(p_h16, batch, Wmu, bmu, Wlv, blv, out, n, g);
}